// round 16
// baseline (speedup 1.0000x reference)
#include <cuda_runtime.h>
#include <cuda_fp16.h>
#include <cstdint>

// ============================================================================
// LocationAwareAttention  B=32, S=2048, D=512   (family-common PTX only:
// mma.sync + ldmatrix + cp.async — NO tcgen05, target is sm_103)
//
// R16: context v4 — two independent load/FMA streams per thread (8 cols x
// 16 rows), doubling loads-in-flight. R15 ncu: context 26.6us @65.9% DRAM,
// issue 7.9% -> single 32-deep acc chain serialized load issue.
// Everything else = R15-proven (149.6us total).
// Output: d_out = [ctx (B*D) | align (B*S)] fp32
// ============================================================================

#define BB 32
#define SS 2048
#define DD 512

__device__ __half g_wvt[DD * DD];          // w_v^T [n][k] fp16
__device__ float  g_qw_part[8 * BB * DD];  // k-split partials of q@w_q(+bias)
__device__ float  g_scores[BB * SS];

// ---------------- SMEM layout (bytes) ----------------
#define SM_A    0                      // 8 chunks x (64x64 fp16, swizzled) = 64KB
#define SM_B    65536                  // 8 warps x 2 stages x 8KB = 128KB
#define SM_QWB  196608
#define SM_CW0  198656
#define SM_CW1  200704
#define SM_CW2  202752
#define SM_SW   204800
#define SM_E0   206848
#define SM_E1   207104
#define SM_E2   207360
#define SM_RED  207616                 // 64 x 8 f32
#define SM_TOT  209664

// ---------------- PTX helpers ----------------
__device__ __forceinline__ uint32_t s2u(const void* p) {
    uint32_t a;
    asm("{ .reg .u64 t; cvta.to.shared.u64 t, %1; cvt.u32.u64 %0, t; }"
        : "=r"(a) : "l"(p));
    return a;
}
__device__ __forceinline__ void cp16(uint32_t dst, const void* src) {
    asm volatile("cp.async.ca.shared.global [%0], [%1], 16;"
                 :: "r"(dst), "l"(src) : "memory");
}
__device__ __forceinline__ void cp_commit() {
    asm volatile("cp.async.commit_group;" ::: "memory");
}
__device__ __forceinline__ void cp_wait0() {
    asm volatile("cp.async.wait_group 0;" ::: "memory");
}
__device__ __forceinline__ void cp_wait1() {
    asm volatile("cp.async.wait_group 1;" ::: "memory");
}
__device__ __forceinline__ void ldsm4(uint32_t& r0, uint32_t& r1,
                                      uint32_t& r2, uint32_t& r3, uint32_t a) {
    asm volatile("ldmatrix.sync.aligned.m8n8.x4.shared.b16 {%0,%1,%2,%3}, [%4];"
                 : "=r"(r0), "=r"(r1), "=r"(r2), "=r"(r3) : "r"(a));
}
__device__ __forceinline__ void mma16816(float* d, const uint32_t* a,
                                         const uint32_t* b) {
    asm volatile(
        "mma.sync.aligned.m16n8k16.row.col.f32.f16.f16.f32 "
        "{%0,%1,%2,%3}, {%4,%5,%6,%7}, {%8,%9}, {%0,%1,%2,%3};"
        : "+f"(d[0]), "+f"(d[1]), "+f"(d[2]), "+f"(d[3])
        : "r"(a[0]), "r"(a[1]), "r"(a[2]), "r"(a[3]), "r"(b[0]), "r"(b[1]));
}
__device__ __forceinline__ float tanh_fast(float x) {
    float y;
    asm("tanh.approx.f32 %0, %1;" : "=f"(y) : "f"(x));
    return y;
}
__device__ __forceinline__ uint32_t packh(__half a, __half b) {
    __half2 h2; h2.x = a; h2.y = b;
    return *(uint32_t*)&h2;
}
__device__ __forceinline__ uint32_t swz(uint32_t row, uint32_t colByte) {
    return row * 128u + (colByte ^ ((row & 7u) << 4));
}

// ============================================================================
// prep (R13-proven): 576 blocks x 256 threads.
// ============================================================================
__global__ void __launch_bounds__(256)
prep_kernel(const float* __restrict__ w_v,
            const float* __restrict__ query,
            const float* __restrict__ w_q,
            const float* __restrict__ bias,
            const float* __restrict__ conv_b) {
    const int blk = blockIdx.x, tid = threadIdx.x;
    if (blk < 64) {
        __shared__ float tile[64][65];
        const int ti = blk >> 3, tj = blk & 7;
#pragma unroll
        for (int q = 0; q < 4; ++q) {
            int idx = q * 256 + tid;
            int r = idx >> 4, c4 = idx & 15;
            float4 v = *(const float4*)(w_v + (size_t)(ti * 64 + r) * DD
                                        + tj * 64 + c4 * 4);
            tile[r][c4 * 4 + 0] = v.x;
            tile[r][c4 * 4 + 1] = v.y;
            tile[r][c4 * 4 + 2] = v.z;
            tile[r][c4 * 4 + 3] = v.w;
        }
        __syncthreads();
#pragma unroll
        for (int q = 0; q < 8; ++q) {
            int slot = q * 256 + tid;
            int nr = slot >> 5, kc = slot & 31;
            __half2 h = __floats2half2_rn(tile[kc * 2][nr],
                                          tile[kc * 2 + 1][nr]);
            *(__half2*)(g_wvt + (size_t)(tj * 64 + nr) * DD + ti * 64 + kc * 2) = h;
        }
    } else {
        const int bb = blk - 64;
        const int ks = bb & 7;
        const int dh = (bb >> 3) & 1;
        const int b  = bb >> 4;
        const int d  = dh * 256 + tid;
        const float* q = query + b * DD + ks * 64;
        const float* w = w_q + (size_t)(ks * 64) * DD + d;
        float a0 = 0.f, a1 = 0.f, a2 = 0.f, a3 = 0.f;
        float a4 = 0.f, a5 = 0.f, a6 = 0.f, a7 = 0.f;
#pragma unroll
        for (int k = 0; k < 64; k += 8) {
            a0 = fmaf(__ldg(q + k),     __ldg(w + (size_t)(k)     * DD), a0);
            a1 = fmaf(__ldg(q + k + 1), __ldg(w + (size_t)(k + 1) * DD), a1);
            a2 = fmaf(__ldg(q + k + 2), __ldg(w + (size_t)(k + 2) * DD), a2);
            a3 = fmaf(__ldg(q + k + 3), __ldg(w + (size_t)(k + 3) * DD), a3);
            a4 = fmaf(__ldg(q + k + 4), __ldg(w + (size_t)(k + 4) * DD), a4);
            a5 = fmaf(__ldg(q + k + 5), __ldg(w + (size_t)(k + 5) * DD), a5);
            a6 = fmaf(__ldg(q + k + 6), __ldg(w + (size_t)(k + 6) * DD), a6);
            a7 = fmaf(__ldg(q + k + 7), __ldg(w + (size_t)(k + 7) * DD), a7);
        }
        float sum = ((a0 + a1) + (a2 + a3)) + ((a4 + a5) + (a6 + a7));
        if (ks == 0) sum += bias[d] + conv_b[d];
        g_qw_part[(ks * BB + b) * DD + d] = sum;
    }
}

// ============================================================================
// scores (R13-proven, byte-identical)
// ============================================================================
__global__ void __launch_bounds__(256, 1)
scores_kernel(const float* __restrict__ value,
              const float* __restrict__ energy,
              const float* __restrict__ conv_w,
              const float* __restrict__ score_w) {
    extern __shared__ char smem[];
    const uint32_t sb = s2u(smem);
    const int tid = threadIdx.x, wid = tid >> 5, lid = tid & 31;
    const int b = blockIdx.x >> 5, tile = blockIdx.x & 31;
    const int s0 = tile * 64;
    const size_t grow0 = (size_t)b * SS + s0;
    const int nwb = wid * 64;

    auto cpB = [&](int ch) {
        const int kb = ch * 64;
        const uint32_t bbuf = sb + SM_B
                            + (uint32_t)((wid << 1) + (ch & 1)) * 8192u;
#pragma unroll
        for (int q = 0; q < 16; ++q) {
            int t = lid + q * 32, n = t >> 3, c = t & 7;
            cp16(bbuf + swz((uint32_t)n, (uint32_t)c * 16),
                 g_wvt + (size_t)(nwb + n) * DD + kb + c * 8);
        }
        cp_commit();
    };

    cpB(0);
    cpB(1);

    float* c_qwb = (float*)(smem + SM_QWB);
    float* c_cw0 = (float*)(smem + SM_CW0);
    float* c_cw1 = (float*)(smem + SM_CW1);
    float* c_cw2 = (float*)(smem + SM_CW2);
    float* c_sw  = (float*)(smem + SM_SW);
    for (int d = tid; d < DD; d += 256) {
        float qsum = 0.f;
#pragma unroll
        for (int ks = 0; ks < 8; ++ks)
            qsum += g_qw_part[(ks * BB + b) * DD + d];
        c_qwb[d] = qsum;
        c_cw0[d] = conv_w[d * 3 + 0];
        c_cw1[d] = conv_w[d * 3 + 1];
        c_cw2[d] = conv_w[d * 3 + 2];
        c_sw[d]  = score_w[d];
    }
    if (tid < 64) {
        int s = s0 + tid, gs = b * SS + s;
        ((float*)(smem + SM_E1))[tid] = energy[gs];
        ((float*)(smem + SM_E0))[tid] = (s > 0)      ? energy[gs - 1] : 0.f;
        ((float*)(smem + SM_E2))[tid] = (s < SS - 1) ? energy[gs + 1] : 0.f;
    }

#pragma unroll
    for (int ch = 0; ch < 8; ++ch) {
        const int kb = ch * 64;
        char* ah = smem + SM_A + ch * 8192;
#pragma unroll
        for (int q = 0; q < 2; ++q) {
            int t = tid * 2 + q, r = t >> 3, c = t & 7;
            const float4* src =
                (const float4*)(value + (grow0 + r) * DD + kb + c * 8);
            float4 v0 = src[0], v1 = src[1];
            uint4 hh;
            hh.x = packh(__float2half_rn(v0.x), __float2half_rn(v0.y));
            hh.y = packh(__float2half_rn(v0.z), __float2half_rn(v0.w));
            hh.z = packh(__float2half_rn(v1.x), __float2half_rn(v1.y));
            hh.w = packh(__float2half_rn(v1.z), __float2half_rn(v1.w));
            *(uint4*)(ah + swz((uint32_t)r, (uint32_t)c * 16)) = hh;
        }
    }
    __syncthreads();

    float acc[4][8][4];
#pragma unroll
    for (int i = 0; i < 4; ++i)
#pragma unroll
        for (int j = 0; j < 8; ++j)
#pragma unroll
            for (int c = 0; c < 4; ++c) acc[i][j][c] = 0.f;

    auto compute = [&](int ch) {
        const uint32_t abuf = sb + SM_A + (uint32_t)ch * 8192u;
        const uint32_t bbuf = sb + SM_B
                            + (uint32_t)((wid << 1) + (ch & 1)) * 8192u;
#pragma unroll
        for (int s = 0; s < 4; ++s) {
            uint32_t bfr[8][2];
#pragma unroll
            for (int np = 0; np < 4; ++np) {
                uint32_t row = np * 16 + ((lid & 16) >> 1) + (lid & 7);
                uint32_t col = s * 32 + ((lid & 8) << 1);
                ldsm4(bfr[np * 2][0], bfr[np * 2][1],
                      bfr[np * 2 + 1][0], bfr[np * 2 + 1][1],
                      bbuf + swz(row, col));
            }
#pragma unroll
            for (int mi = 0; mi < 4; ++mi) {
                uint32_t row = mi * 16 + (lid & 15);
                uint32_t col = s * 32 + (lid & 16);
                uint32_t ah[4];
                ldsm4(ah[0], ah[1], ah[2], ah[3], abuf + swz(row, col));
#pragma unroll
                for (int ni = 0; ni < 8; ++ni)
                    mma16816(acc[mi][ni], ah, bfr[ni]);
            }
        }
    };

    for (int ch = 0; ch < 8; ++ch) {
        if (ch < 7) cp_wait1();
        else        cp_wait0();
        __syncwarp();
        compute(ch);
        if (ch < 6) cpB(ch + 2);
    }

    const float* E0 = (const float*)(smem + SM_E0);
    const float* E1 = (const float*)(smem + SM_E1);
    const float* E2 = (const float*)(smem + SM_E2);
    float e0r[8], e1r[8], e2r[8];
#pragma unroll
    for (int mi = 0; mi < 4; ++mi)
#pragma unroll
        for (int h = 0; h < 2; ++h) {
            int r = mi * 16 + h * 8 + (lid >> 2);
            e0r[mi * 2 + h] = E0[r];
            e1r[mi * 2 + h] = E1[r];
            e2r[mi * 2 + h] = E2[r];
        }
    float part[8];
#pragma unroll
    for (int i = 0; i < 8; ++i) part[i] = 0.f;

#pragma unroll
    for (int ni = 0; ni < 8; ++ni) {
        int d0 = nwb + ni * 8 + 2 * (lid & 3);
        float qb0 = c_qwb[d0], qb1 = c_qwb[d0 + 1];
        float w00 = c_cw0[d0], w01 = c_cw0[d0 + 1];
        float w10 = c_cw1[d0], w11 = c_cw1[d0 + 1];
        float w20 = c_cw2[d0], w21 = c_cw2[d0 + 1];
        float sw0 = c_sw[d0],  sw1 = c_sw[d0 + 1];
#pragma unroll
        for (int mi = 0; mi < 4; ++mi)
#pragma unroll
            for (int h = 0; h < 2; ++h) {
                int pi = mi * 2 + h;
                float x0 = acc[mi][ni][h * 2] + qb0
                         + e0r[pi] * w00 + e1r[pi] * w10 + e2r[pi] * w20;
                float x1 = acc[mi][ni][h * 2 + 1] + qb1
                         + e0r[pi] * w01 + e1r[pi] * w11 + e2r[pi] * w21;
                part[pi] = fmaf(tanh_fast(x0), sw0,
                                fmaf(tanh_fast(x1), sw1, part[pi]));
            }
    }
#pragma unroll
    for (int pi = 0; pi < 8; ++pi) {
        part[pi] += __shfl_xor_sync(0xffffffffu, part[pi], 1);
        part[pi] += __shfl_xor_sync(0xffffffffu, part[pi], 2);
    }
    float* red = (float*)(smem + SM_RED);
    if ((lid & 3) == 0) {
#pragma unroll
        for (int mi = 0; mi < 4; ++mi)
#pragma unroll
            for (int h = 0; h < 2; ++h) {
                int r = mi * 16 + h * 8 + (lid >> 2);
                red[r * 8 + wid] = part[mi * 2 + h];
            }
    }
    __syncthreads();
    if (tid < 64) {
        float sum = 0.f;
#pragma unroll
        for (int w = 0; w < 8; ++w) sum += red[tid * 8 + w];
        g_scores[b * SS + s0 + tid] = sum;
    }
}

// ============================================================================
// softmax per batch -> align; also zeroes ctx[b] (context runs after).
// ============================================================================
__global__ void softmax_kernel(float* __restrict__ align_out,
                               float* __restrict__ ctx) {
    __shared__ float wred[8];
    int b = blockIdx.x, t = threadIdx.x, w = t >> 5, l = t & 31;
    ((float2*)(ctx + b * DD))[t] = make_float2(0.f, 0.f);

    const float4* s4 = (const float4*)(g_scores + b * SS);
    float4 v0 = s4[t];
    float4 v1 = s4[t + 256];
    float m = fmaxf(fmaxf(fmaxf(v0.x, v0.y), fmaxf(v0.z, v0.w)),
                    fmaxf(fmaxf(v1.x, v1.y), fmaxf(v1.z, v1.w)));
#pragma unroll
    for (int o = 16; o > 0; o >>= 1)
        m = fmaxf(m, __shfl_xor_sync(0xffffffffu, m, o));
    if (l == 0) wred[w] = m;
    __syncthreads();
    m = wred[0];
#pragma unroll
    for (int i = 1; i < 8; ++i) m = fmaxf(m, wred[i]);
    __syncthreads();

    float4 e0, e1;
    e0.x = __expf(v0.x - m); e0.y = __expf(v0.y - m);
    e0.z = __expf(v0.z - m); e0.w = __expf(v0.w - m);
    e1.x = __expf(v1.x - m); e1.y = __expf(v1.y - m);
    e1.z = __expf(v1.z - m); e1.w = __expf(v1.w - m);
    float sum = e0.x + e0.y + e0.z + e0.w + e1.x + e1.y + e1.z + e1.w;
#pragma unroll
    for (int o = 16; o > 0; o >>= 1)
        sum += __shfl_xor_sync(0xffffffffu, sum, o);
    if (l == 0) wred[w] = sum;
    __syncthreads();
    sum = wred[0];
#pragma unroll
    for (int i = 1; i < 8; ++i) sum += wred[i];
    float inv = 1.f / sum;
    e0.x *= inv; e0.y *= inv; e0.z *= inv; e0.w *= inv;
    e1.x *= inv; e1.y *= inv; e1.z *= inv; e1.w *= inv;
    float4* a4 = (float4*)(align_out + b * SS);
    a4[t] = e0;
    a4[t + 256] = e1;
}

// ============================================================================
// context v4: grid (B, 32 s-chunks) x 256 threads; thread covers 8 cols
// (2 independent float4 streams) x 16 s-rows. Block = 64 s x 512 d.
// ct = t&63 -> cols [ct*8, ct*8+8); sq = t>>6 -> rows [sq*16, sq*16+16).
// ============================================================================
__global__ void __launch_bounds__(256)
context_kernel(const float* __restrict__ value,
               const float* __restrict__ align,
               float* __restrict__ ctx) {
    __shared__ float al[64];
    __shared__ float4 pc0[256];
    __shared__ float4 pc1[256];
    const int b = blockIdx.x, sch = blockIdx.y;
    const int t = threadIdx.x;
    if (t < 64) al[t] = align[b * SS + sch * 64 + t];
    __syncthreads();

    const int ct = t & 63;             // col group: cols [8*ct, 8*ct+8)
    const int sq = t >> 6;             // s-quarter: rows [sq*16, sq*16+16)
    const float4* vb = (const float4*)(value
                        + ((size_t)b * SS + sch * 64 + sq * 16) * DD) + ct * 2;
    const float* ab = al + sq * 16;
    float4 a0 = make_float4(0.f, 0.f, 0.f, 0.f);
    float4 a1 = make_float4(0.f, 0.f, 0.f, 0.f);
#pragma unroll
    for (int s = 0; s < 16; ++s) {
        float4 v0 = vb[(size_t)s * (DD / 4)];
        float4 v1 = vb[(size_t)s * (DD / 4) + 1];
        float a = ab[s];
        a0.x = fmaf(a, v0.x, a0.x);
        a0.y = fmaf(a, v0.y, a0.y);
        a0.z = fmaf(a, v0.z, a0.z);
        a0.w = fmaf(a, v0.w, a0.w);
        a1.x = fmaf(a, v1.x, a1.x);
        a1.y = fmaf(a, v1.y, a1.y);
        a1.z = fmaf(a, v1.z, a1.z);
        a1.w = fmaf(a, v1.w, a1.w);
    }
    pc0[t] = a0;
    pc1[t] = a1;
    __syncthreads();
    if (t < 128) {
        const int which = t >> 6;      // 0 -> pc0 (cols +0), 1 -> pc1 (cols +4)
        const int cg = t & 63;
        const float4* pc = which ? pc1 : pc0;
        float4 p0 = pc[cg], p1 = pc[cg + 64], p2 = pc[cg + 128], p3 = pc[cg + 192];
        float* dst = ctx + b * DD + cg * 8 + which * 4;
        atomicAdd(dst + 0, ((p0.x + p1.x) + (p2.x + p3.x)));
        atomicAdd(dst + 1, ((p0.y + p1.y) + (p2.y + p3.y)));
        atomicAdd(dst + 2, ((p0.z + p1.z) + (p2.z + p3.z)));
        atomicAdd(dst + 3, ((p0.w + p1.w) + (p2.w + p3.w)));
    }
}

// ============================================================================
// launch (4 kernels)
// ============================================================================
extern "C" void kernel_launch(void* const* d_in, const int* in_sizes, int n_in,
                              void* d_out, int out_size) {
    const float* query   = (const float*)d_in[0];
    const float* value   = (const float*)d_in[1];
    const float* energy  = (const float*)d_in[2];
    const float* conv_w  = (const float*)d_in[3];
    const float* conv_b  = (const float*)d_in[4];
    const float* w_q     = (const float*)d_in[5];
    const float* w_v     = (const float*)d_in[6];
    const float* bias    = (const float*)d_in[7];
    const float* score_w = (const float*)d_in[8];
    float* out_ctx   = (float*)d_out;            // [B*D]
    float* out_align = (float*)d_out + BB * DD;  // [B*S]

    cudaFuncSetAttribute(scores_kernel,
                         cudaFuncAttributeMaxDynamicSharedMemorySize, SM_TOT);

    prep_kernel<<<576, 256>>>(w_v, query, w_q, bias, conv_b);
    scores_kernel<<<BB * 32, 256, SM_TOT>>>(value, energy, conv_w, score_w);
    softmax_kernel<<<BB, 256>>>(out_align, out_ctx);
    context_kernel<<<dim3(BB, 32), 256>>>(value, out_align, out_ctx);
}